// round 16
// baseline (speedup 1.0000x reference)
#include <cuda_runtime.h>
#include <stdint.h>

// ---------------------------------------------------------------------------
// DownsampleWithPruning — sparse stride-2 conv (2x2x2) + prune by ref set.
// Keyspace: b<<24 | x<<16 | y<<8 | z  in [0, 2^26)
//
// DAG (5 nodes):
//   s0: memsetAsync  256MB feats zeros
//   sB: k_setup      state reset + ref bitmap + packed keys + parent bitmap
//       k_scan       dual lookback scan (warp-parallel lookback) ->
//                    coords+mask staged emit, rankBase, masked-rank list
//       k_contrib    g_keys -> g_contrib[rank*8+tap]=i+1 (unique writer)
//   s0: join -> k_tail  pad [M,N); bias atomics; TAP-PINNED conv:
//                       W slice in regs loaded once per warp, inner loop is
//                       shfl+FMA only, atomicAdd accumulation.
// ---------------------------------------------------------------------------

#define WORDS   (1 << 20)       // 2^26 keys / 64
#define NCHUNK  1024            // scan chunks (1024 words each)
#define CWORDS  1024
#define MASK21  0x1FFFFFull
#define FULLM   0xffffffffu
#define SCAP    2048            // staged keys per chunk

__device__ unsigned long long g_bitmap[WORDS];   // parent-key occupancy (8MB)
__device__ unsigned long long g_refbit[WORDS];   // ref-key occupancy (8MB)
__device__ unsigned long long g_state[NCHUNK];   // flag<<62 | rank<<21 | mask
__device__ int g_rankBase[WORDS];                // global rank at word start
__device__ int g_keys[1 << 20];                  // packed input keys (4MB)
__device__ int g_masked[1 << 20];                // ranks of masked outputs
__device__ int g_contrib[8 * (1 << 20)];         // (rank,tap) -> input idx+1
__device__ int g_M;                              // unique outputs
__device__ int g_mTotal;                         // masked outputs

// ---- setup: state reset + ref bitmap + keys + parent bitmap ------------------
__global__ void __launch_bounds__(256) k_setup(const int* __restrict__ coords, int N,
                                               const int* __restrict__ rc, int NR) {
    int tid = blockIdx.x * blockDim.x + threadIdx.x;
    int T = gridDim.x * blockDim.x;
    if (tid < NCHUNK) g_state[tid] = 0ull;

    const int4* rc4 = (const int4*)rc;
#pragma unroll 2
    for (int i = tid; i < NR; i += T) {
        int4 c = rc4[i];
        int key = (c.x << 24) | (c.y << 16) | (c.z << 8) | c.w;
        atomicOr(&g_refbit[key >> 6], 1ull << (key & 63));
    }
    const int4* c4 = (const int4*)coords;
#pragma unroll 2
    for (int i = tid; i < N; i += T) {
        int4 c = c4[i];
        int key = (c.x << 24) | (c.y << 16) | (c.z << 8) | c.w;
        g_keys[i] = key;
        int pkey = key & ~0x00010101;
        atomicOr(&g_bitmap[pkey >> 6], 1ull << (pkey & 63));
    }
}

// ---- dual lookback scan (warp-parallel lookback); staged coalesced emit -------
__global__ void __launch_bounds__(256) k_scan(float* __restrict__ out,
                                              long long maskBase) {
    __shared__ unsigned long long s_wsum[8];
    __shared__ int s_exR, s_exM;
    __shared__ int s_keys[SCAP];
    const int tid  = threadIdx.x;
    const int lane = tid & 31;
    const int wid  = tid >> 5;
    const int b    = blockIdx.x;

    int base = b * CWORDS + tid * 4;
    unsigned long long w[4], mw[4];
    int s = 0, m = 0;
#pragma unroll
    for (int j = 0; j < 4; j++) {
        w[j]  = g_bitmap[base + j];
        mw[j] = w[j] & g_refbit[base + j];
        s += __popcll(w[j]);
        m += __popcll(mw[j]);
    }
    unsigned long long x = ((unsigned long long)s << 32) | (unsigned)m;
#pragma unroll
    for (int o = 1; o < 32; o <<= 1) {
        unsigned long long y = __shfl_up_sync(FULLM, x, o);
        if (lane >= o) x += y;
    }
    if (lane == 31) s_wsum[wid] = x;
    __syncthreads();
    if (wid == 0) {
        unsigned long long t = (lane < 8) ? s_wsum[lane] : 0ull;
#pragma unroll
        for (int o = 1; o < 8; o <<= 1) {
            unsigned long long y = __shfl_up_sync(FULLM, t, o);
            if (lane >= o) t += y;
        }
        if (lane < 8) s_wsum[lane] = t;
    }
    __syncthreads();
    unsigned long long incl = (wid ? s_wsum[wid - 1] : 0ull) + x;
    int thrExR = (int)(incl >> 32) - s;               // block-local
    int thrExM = (int)(incl & 0xFFFFFFFFull) - m;
    int aggR = (int)(s_wsum[7] >> 32);
    int aggM = (int)(s_wsum[7] & 0xFFFFFFFFull);

    // warp 0: warp-parallel decoupled lookback
    if (wid == 0) {
        long long exR = 0, exM = 0;
        if (b == 0) {
            if (lane == 0)
                atomicExch(&g_state[0], (2ull << 62) |
                           ((unsigned long long)aggR << 21) |
                           (unsigned long long)aggM);
        } else {
            if (lane == 0)
                atomicExch(&g_state[b], (1ull << 62) |
                           ((unsigned long long)aggR << 21) |
                           (unsigned long long)aggM);
            int j = b - 1;
            while (true) {
                int idx = j - lane;
                unsigned long long v = (idx >= 0)
                    ? *((volatile unsigned long long*)&g_state[idx])
                    : (2ull << 62);                   // virtual flag2, value 0
                unsigned f = (unsigned)(v >> 62);
                unsigned b2 = __ballot_sync(FULLM, f == 2);
                unsigned b0 = __ballot_sync(FULLM, f == 0);
                int f2 = b2 ? (__ffs(b2) - 1) : 32;
                int f0 = b0 ? (__ffs(b0) - 1) : 32;
                if (f0 < f2) continue;                // not ready: retry window
                int rv = 0, mv = 0;
                if (lane <= f2) {
                    rv = (int)((v >> 21) & MASK21);
                    mv = (int)(v & MASK21);
                }
#pragma unroll
                for (int o = 16; o; o >>= 1) {
                    rv += __shfl_down_sync(FULLM, rv, o);
                    mv += __shfl_down_sync(FULLM, mv, o);
                }
                rv = __shfl_sync(FULLM, rv, 0);
                mv = __shfl_sync(FULLM, mv, 0);
                exR += rv; exM += mv;
                if (f2 < 32) break;
                j -= 32;
            }
            if (lane == 0)
                atomicExch(&g_state[b], (2ull << 62) |
                           ((unsigned long long)(exR + aggR) << 21) |
                           (unsigned long long)(exM + aggM));
        }
        if (lane == 0) {
            s_exR = (int)exR;
            s_exM = (int)exM;
            if (b == NCHUNK - 1) { g_M = (int)exR + aggR; g_mTotal = (int)exM + aggM; }
        }
    }
    __syncthreads();

    bool useStage = (aggR <= SCAP);
    int exR = s_exR;
    int lrank = thrExR;                               // block-local rank
    int mrank = s_exM + thrExM;                       // global masked index
    int rb[4];
#pragma unroll
    for (int j = 0; j < 4; j++) {
        rb[j] = exR + lrank;
        unsigned long long ww = w[j], mm = mw[j];
        int keyhi = (base + j) << 6;
        while (ww) {
            int bpos = __ffsll((long long)ww) - 1;
            ww &= ww - 1;
            int k = keyhi | bpos;
            bool msk = (mm >> bpos) & 1ull;
            if (useStage) {
                s_keys[lrank] = k | (msk ? 0x80000000 : 0);
            } else {
                __stcs(&((float4*)out)[exR + lrank],
                       make_float4((float)(k >> 24), (float)((k >> 16) & 255),
                                   (float)((k >> 8) & 255), (float)(k & 255)));
                __stcs(&out[maskBase + exR + lrank], msk ? 1.0f : 0.0f);
            }
            if (msk) g_masked[mrank++] = exR + lrank;
            lrank++;
        }
    }
    *((int4*)&g_rankBase[base]) = make_int4(rb[0], rb[1], rb[2], rb[3]);

    if (useStage) {
        __syncthreads();
        for (int idx = tid; idx < aggR; idx += 256) {
            int kk = s_keys[idx];
            int k = kk & 0x03FFFFFF;
            __stcs(&((float4*)out)[exR + idx],
                   make_float4((float)(k >> 24), (float)((k >> 16) & 255),
                               (float)((k >> 8) & 255), (float)(k & 255)));
            __stcs(&out[maskBase + exR + idx],
                   ((unsigned)kk >> 31) ? 1.0f : 0.0f);
        }
    }
}

// ---- contributions: packed keys -> (parent rank, tap) slot ---------------------
__global__ void __launch_bounds__(256) k_contrib(int N) {
    int tid = blockIdx.x * blockDim.x + threadIdx.x;
    int T = gridDim.x * blockDim.x;
    for (int i = tid; i < N; i += T) {
        int key  = g_keys[i];
        int pkey = key & ~0x00010101;
        int word = pkey >> 6, bit = pkey & 63;
        if ((g_refbit[word] >> bit) & 1ull) {
            int rank = g_rankBase[word] +
                       __popcll(g_bitmap[word] & ((1ull << bit) - 1ull));
            int tap = ((key >> 14) & 4) | ((key >> 7) & 2) | (key & 1);
            g_contrib[rank * 8 + tap] = i + 1;       // unique writer per slot
        }
    }
}

// ---- tail: pad [M,N) + bias atomics + TAP-PINNED conv (W in regs, no loads) ---
__global__ void __launch_bounds__(256) k_tail(const float* __restrict__ feats,
                                              const float* __restrict__ W,
                                              const float* __restrict__ bias,
                                              float* __restrict__ out,
                                              int N,
                                              long long featBase,
                                              long long maskBase) {
    const int lane = threadIdx.x & 31;
    const int gtid = blockIdx.x * blockDim.x + threadIdx.x;
    const int Tthr = gridDim.x * blockDim.x;
    const int gw   = gtid >> 5;
    const int totalWarps = Tthr >> 5;

    // pad coords + mask rows [M, N)
    int M = g_M;
    float4 neg1 = make_float4(-1.f, -1.f, -1.f, -1.f);
    for (int r = M + gtid; r < N; r += Tthr) {
        __stcs(&((float4*)out)[r], neg1);
        __stcs(&out[maskBase + r], 0.0f);
    }

    int mc = g_mTotal;

    // bias adds (order-free with conv atomics below)
    float b0 = __ldg(&bias[lane]);
    float b1 = __ldg(&bias[32 + lane]);
    for (int i = gw; i < mc; i += totalWarps) {
        int r = g_masked[i];
        float* dst = out + featBase + (long long)r * 64;
        atomicAdd(dst + lane, b0);
        atomicAdd(dst + 32 + lane, b1);
    }

    // tap-pinned conv: W slice in regs loaded ONCE; inner loop shfl+FMA only
    int tap = gw & 7;
    float2 wreg[32];
    const float* Wt = W + tap * 2048;
#pragma unroll
    for (int j = 0; j < 32; j++)
        wreg[j] = make_float2(__ldg(&Wt[j * 64 + lane]),
                              __ldg(&Wt[j * 64 + 32 + lane]));

    int i0   = gw >> 3;
    int step = totalWarps >> 3;
    for (int i = i0; i < mc; i += step) {
        int r = g_masked[i];
        int v = __ldg(&g_contrib[r * 8 + tap]);      // broadcast load
        if (v == 0) continue;
        float f = __ldg(&feats[(long long)(v - 1) * 32 + lane]);
        float a0 = 0.f, a1 = 0.f;
#pragma unroll
        for (int j = 0; j < 32; j++) {
            float fj = __shfl_sync(FULLM, f, j);
            a0 += fj * wreg[j].x;
            a1 += fj * wreg[j].y;
        }
        float* dst = out + featBase + (long long)r * 64;
        atomicAdd(dst + lane, a0);
        atomicAdd(dst + 32 + lane, a1);
    }
}

// ---- streams/events created at load time (no device-memory allocation) -----
static cudaStream_t g_sB;
static cudaEvent_t  g_evFork, g_evEmit;
namespace {
struct ResInit {
    ResInit() {
        cudaStreamCreateWithFlags(&g_sB, cudaStreamNonBlocking);
        cudaEventCreateWithFlags(&g_evFork, cudaEventDisableTiming);
        cudaEventCreateWithFlags(&g_evEmit, cudaEventDisableTiming);
    }
};
static ResInit g_resInit;
}

extern "C" void kernel_launch(void* const* d_in, const int* in_sizes, int n_in,
                              void* d_out, int out_size) {
    const float* feats  = (const float*)d_in[0];
    const float* W      = (const float*)d_in[1];
    const float* bias   = (const float*)d_in[2];
    const int*   coords = (const int*)d_in[3];
    const int*   ref    = (const int*)d_in[4];
    float* out = (float*)d_out;

    int N  = in_sizes[3] / 4;
    int NR = in_sizes[4] / 4;
    long long featBase = 4LL * N;
    long long maskBase = (long long)out_size - N;   // == 68N
    long long featLen  = 64LL * N;                  // feats region only

    cudaEventRecord(g_evFork, 0);
    cudaStreamWaitEvent(g_sB, g_evFork, 0);

    // s0: driver fill of the feats region
    cudaMemsetAsync(out + featBase, 0, featLen * sizeof(float), 0);

    // sB: setup -> scan -> contrib
    k_setup<<<1184, 256, 0, g_sB>>>(coords, N, ref, NR);
    k_scan<<<NCHUNK, 256, 0, g_sB>>>(out, maskBase);
    k_contrib<<<1184, 256, 0, g_sB>>>(N);
    cudaEventRecord(g_evEmit, g_sB);

    // s0: join -> tap-pinned tail
    cudaStreamWaitEvent(0, g_evEmit, 0);
    k_tail<<<1184, 256, 0, 0>>>(feats, W, bias, out, N, featBase, maskBase);
}

// round 17
// speedup vs baseline: 1.4744x; 1.4744x over previous
#include <cuda_runtime.h>
#include <stdint.h>

// ---------------------------------------------------------------------------
// DownsampleWithPruning — sparse stride-2 conv (2x2x2) + prune by ref set.
// Keyspace: b<<24 | x<<16 | y<<8 | z  in [0, 2^26)
//
// DAG:
//   s0: memsetAsync  256MB feats zeros
//   sB: k_setup   -> k_scan (coords+mask emit, rankBase, masked list)
//       k_contrib -> k_conv (masked rows -> compact g_scratch; pad [M,N))
//       [all hidden under the fill]
//   s0: join -> k_copy  scatter-copy scratch rows into out (24MB, ~8us)
// ---------------------------------------------------------------------------

#define WORDS   (1 << 20)       // 2^26 keys / 64
#define NCHUNK  1024            // scan chunks (1024 words each)
#define CWORDS  1024
#define MASK21  0x1FFFFFull
#define FULLM   0xffffffffu
#define SCAP    2048            // staged keys per chunk

__device__ unsigned long long g_bitmap[WORDS];   // parent-key occupancy (8MB)
__device__ unsigned long long g_refbit[WORDS];   // ref-key occupancy (8MB)
__device__ unsigned long long g_state[NCHUNK];   // flag<<62 | rank<<21 | mask
__device__ int g_rankBase[WORDS];                // global rank at word start
__device__ int g_keys[1 << 20];                  // packed input keys (4MB)
__device__ int g_masked[1 << 20];                // ranks of masked outputs
__device__ int g_contrib[8 * (1 << 20)];         // (rank,tap) -> input idx+1
__device__ float g_scratch[(long long)(1 << 20) * 64]; // compact masked rows
__device__ int g_M;                              // unique outputs
__device__ int g_mTotal;                         // masked outputs

// ---- setup: state reset + ref bitmap + keys + parent bitmap ------------------
__global__ void __launch_bounds__(256) k_setup(const int* __restrict__ coords, int N,
                                               const int* __restrict__ rc, int NR) {
    int tid = blockIdx.x * blockDim.x + threadIdx.x;
    int T = gridDim.x * blockDim.x;
    if (tid < NCHUNK) g_state[tid] = 0ull;

    const int4* rc4 = (const int4*)rc;
#pragma unroll 2
    for (int i = tid; i < NR; i += T) {
        int4 c = rc4[i];
        int key = (c.x << 24) | (c.y << 16) | (c.z << 8) | c.w;
        atomicOr(&g_refbit[key >> 6], 1ull << (key & 63));
    }
    const int4* c4 = (const int4*)coords;
#pragma unroll 2
    for (int i = tid; i < N; i += T) {
        int4 c = c4[i];
        int key = (c.x << 24) | (c.y << 16) | (c.z << 8) | c.w;
        g_keys[i] = key;
        int pkey = key & ~0x00010101;
        atomicOr(&g_bitmap[pkey >> 6], 1ull << (pkey & 63));
    }
}

// ---- dual lookback scan (warp-parallel lookback); staged coalesced emit -------
__global__ void __launch_bounds__(256) k_scan(float* __restrict__ out,
                                              long long maskBase) {
    __shared__ unsigned long long s_wsum[8];
    __shared__ int s_exR, s_exM;
    __shared__ int s_keys[SCAP];
    const int tid  = threadIdx.x;
    const int lane = tid & 31;
    const int wid  = tid >> 5;
    const int b    = blockIdx.x;

    int base = b * CWORDS + tid * 4;
    unsigned long long w[4], mw[4];
    int s = 0, m = 0;
#pragma unroll
    for (int j = 0; j < 4; j++) {
        w[j]  = g_bitmap[base + j];
        mw[j] = w[j] & g_refbit[base + j];
        s += __popcll(w[j]);
        m += __popcll(mw[j]);
    }
    unsigned long long x = ((unsigned long long)s << 32) | (unsigned)m;
#pragma unroll
    for (int o = 1; o < 32; o <<= 1) {
        unsigned long long y = __shfl_up_sync(FULLM, x, o);
        if (lane >= o) x += y;
    }
    if (lane == 31) s_wsum[wid] = x;
    __syncthreads();
    if (wid == 0) {
        unsigned long long t = (lane < 8) ? s_wsum[lane] : 0ull;
#pragma unroll
        for (int o = 1; o < 8; o <<= 1) {
            unsigned long long y = __shfl_up_sync(FULLM, t, o);
            if (lane >= o) t += y;
        }
        if (lane < 8) s_wsum[lane] = t;
    }
    __syncthreads();
    unsigned long long incl = (wid ? s_wsum[wid - 1] : 0ull) + x;
    int thrExR = (int)(incl >> 32) - s;               // block-local
    int thrExM = (int)(incl & 0xFFFFFFFFull) - m;
    int aggR = (int)(s_wsum[7] >> 32);
    int aggM = (int)(s_wsum[7] & 0xFFFFFFFFull);

    if (wid == 0) {                                    // warp-parallel lookback
        long long exR = 0, exM = 0;
        if (b == 0) {
            if (lane == 0)
                atomicExch(&g_state[0], (2ull << 62) |
                           ((unsigned long long)aggR << 21) |
                           (unsigned long long)aggM);
        } else {
            if (lane == 0)
                atomicExch(&g_state[b], (1ull << 62) |
                           ((unsigned long long)aggR << 21) |
                           (unsigned long long)aggM);
            int j = b - 1;
            while (true) {
                int idx = j - lane;
                unsigned long long v = (idx >= 0)
                    ? *((volatile unsigned long long*)&g_state[idx])
                    : (2ull << 62);
                unsigned f = (unsigned)(v >> 62);
                unsigned b2 = __ballot_sync(FULLM, f == 2);
                unsigned b0 = __ballot_sync(FULLM, f == 0);
                int f2 = b2 ? (__ffs(b2) - 1) : 32;
                int f0 = b0 ? (__ffs(b0) - 1) : 32;
                if (f0 < f2) continue;
                int rv = 0, mv = 0;
                if (lane <= f2) {
                    rv = (int)((v >> 21) & MASK21);
                    mv = (int)(v & MASK21);
                }
#pragma unroll
                for (int o = 16; o; o >>= 1) {
                    rv += __shfl_down_sync(FULLM, rv, o);
                    mv += __shfl_down_sync(FULLM, mv, o);
                }
                rv = __shfl_sync(FULLM, rv, 0);
                mv = __shfl_sync(FULLM, mv, 0);
                exR += rv; exM += mv;
                if (f2 < 32) break;
                j -= 32;
            }
            if (lane == 0)
                atomicExch(&g_state[b], (2ull << 62) |
                           ((unsigned long long)(exR + aggR) << 21) |
                           (unsigned long long)(exM + aggM));
        }
        if (lane == 0) {
            s_exR = (int)exR;
            s_exM = (int)exM;
            if (b == NCHUNK - 1) { g_M = (int)exR + aggR; g_mTotal = (int)exM + aggM; }
        }
    }
    __syncthreads();

    bool useStage = (aggR <= SCAP);
    int exR = s_exR;
    int lrank = thrExR;
    int mrank = s_exM + thrExM;
    int rb[4];
#pragma unroll
    for (int j = 0; j < 4; j++) {
        rb[j] = exR + lrank;
        unsigned long long ww = w[j], mm = mw[j];
        int keyhi = (base + j) << 6;
        while (ww) {
            int bpos = __ffsll((long long)ww) - 1;
            ww &= ww - 1;
            int k = keyhi | bpos;
            bool msk = (mm >> bpos) & 1ull;
            if (useStage) {
                s_keys[lrank] = k | (msk ? 0x80000000 : 0);
            } else {
                __stcs(&((float4*)out)[exR + lrank],
                       make_float4((float)(k >> 24), (float)((k >> 16) & 255),
                                   (float)((k >> 8) & 255), (float)(k & 255)));
                __stcs(&out[maskBase + exR + lrank], msk ? 1.0f : 0.0f);
            }
            if (msk) g_masked[mrank++] = exR + lrank;
            lrank++;
        }
    }
    *((int4*)&g_rankBase[base]) = make_int4(rb[0], rb[1], rb[2], rb[3]);

    if (useStage) {
        __syncthreads();
        for (int idx = tid; idx < aggR; idx += 256) {
            int kk = s_keys[idx];
            int k = kk & 0x03FFFFFF;
            __stcs(&((float4*)out)[exR + idx],
                   make_float4((float)(k >> 24), (float)((k >> 16) & 255),
                               (float)((k >> 8) & 255), (float)(k & 255)));
            __stcs(&out[maskBase + exR + idx],
                   ((unsigned)kk >> 31) ? 1.0f : 0.0f);
        }
    }
}

// ---- contributions: packed keys -> (parent rank, tap) slot ---------------------
__global__ void __launch_bounds__(256) k_contrib(int N) {
    int tid = blockIdx.x * blockDim.x + threadIdx.x;
    int T = gridDim.x * blockDim.x;
    for (int i = tid; i < N; i += T) {
        int key  = g_keys[i];
        int pkey = key & ~0x00010101;
        int word = pkey >> 6, bit = pkey & 63;
        if ((g_refbit[word] >> bit) & 1ull) {
            int rank = g_rankBase[word] +
                       __popcll(g_bitmap[word] & ((1ull << bit) - 1ull));
            int tap = ((key >> 14) & 4) | ((key >> 7) & 2) | (key & 1);
            g_contrib[rank * 8 + tap] = i + 1;       // unique writer per slot
        }
    }
}

// ---- conv (in chain, hidden under fill): masked rows -> compact scratch ------
//      also pads coords + mask rows [M, N) (regions not covered by memset)
__global__ void __launch_bounds__(256) k_conv(const float* __restrict__ feats,
                                              const float* __restrict__ W,
                                              const float* __restrict__ bias,
                                              float* __restrict__ out,
                                              int N,
                                              long long maskBase) {
    const int lane = threadIdx.x & 31;
    const int gtid = blockIdx.x * blockDim.x + threadIdx.x;
    const int Tthr = gridDim.x * blockDim.x;
    const int gw   = gtid >> 5;
    const int totalWarps = Tthr >> 5;

    // pad coords + mask rows [M, N)
    int M = g_M;
    float4 neg1 = make_float4(-1.f, -1.f, -1.f, -1.f);
    for (int r = M + gtid; r < N; r += Tthr) {
        __stcs(&((float4*)out)[r], neg1);
        __stcs(&out[maskBase + r], 0.0f);
    }

    float2 bv = ((const float2*)bias)[lane];
    int mc = g_mTotal;
    for (int i = gw; i < mc; i += totalWarps) {
        int r = g_masked[i];
        int v = (lane < 8) ? g_contrib[r * 8 + lane] : 0;
        unsigned act = __ballot_sync(FULLM, v != 0) & 0xFFu;
        float2 acc = bv;
        while (act) {
            int t = __ffs(act) - 1;
            act &= act - 1;
            int n = __shfl_sync(FULLM, v, t) - 1;
            float f = __ldg(&feats[(long long)n * 32 + lane]);
            const float2* Wt = (const float2*)(W + t * 2048);
#pragma unroll
            for (int j = 0; j < 32; j++) {
                float fj = __shfl_sync(FULLM, f, j);
                float2 wv = __ldg(&Wt[j * 32 + lane]);
                acc.x += fj * wv.x;
                acc.y += fj * wv.y;
            }
        }
        ((float2*)(g_scratch + (long long)i * 64))[lane] = acc;  // coalesced
    }
}

// ---- tail (exposed): scatter-copy scratch rows into out -----------------------
__global__ void __launch_bounds__(256) k_copy(float* __restrict__ out,
                                              long long featBase) {
    const int lane = threadIdx.x & 31;
    const int gw   = (blockIdx.x * blockDim.x + threadIdx.x) >> 5;
    const int totalWarps = (gridDim.x * blockDim.x) >> 5;
    int mc = g_mTotal;
    for (int i = gw; i < mc; i += totalWarps) {
        int r = g_masked[i];
        float2 v = ((const float2*)(g_scratch + (long long)i * 64))[lane];
        ((float2*)(out + featBase + (long long)r * 64))[lane] = v;
    }
}

// ---- streams/events created at load time (no device-memory allocation) -----
static cudaStream_t g_sB;
static cudaEvent_t  g_evFork, g_evEmit;
namespace {
struct ResInit {
    ResInit() {
        cudaStreamCreateWithFlags(&g_sB, cudaStreamNonBlocking);
        cudaEventCreateWithFlags(&g_evFork, cudaEventDisableTiming);
        cudaEventCreateWithFlags(&g_evEmit, cudaEventDisableTiming);
    }
};
static ResInit g_resInit;
}

extern "C" void kernel_launch(void* const* d_in, const int* in_sizes, int n_in,
                              void* d_out, int out_size) {
    const float* feats  = (const float*)d_in[0];
    const float* W      = (const float*)d_in[1];
    const float* bias   = (const float*)d_in[2];
    const int*   coords = (const int*)d_in[3];
    const int*   ref    = (const int*)d_in[4];
    float* out = (float*)d_out;

    int N  = in_sizes[3] / 4;
    int NR = in_sizes[4] / 4;
    long long featBase = 4LL * N;
    long long maskBase = (long long)out_size - N;   // == 68N
    long long featLen  = 64LL * N;                  // feats region only

    cudaEventRecord(g_evFork, 0);
    cudaStreamWaitEvent(g_sB, g_evFork, 0);

    // s0: driver fill of the feats region
    cudaMemsetAsync(out + featBase, 0, featLen * sizeof(float), 0);

    // sB (hidden under the fill): setup -> scan -> contrib -> conv(scratch)
    k_setup<<<1184, 256, 0, g_sB>>>(coords, N, ref, NR);
    k_scan<<<NCHUNK, 256, 0, g_sB>>>(out, maskBase);
    k_contrib<<<1184, 256, 0, g_sB>>>(N);
    k_conv<<<1184, 256, 0, g_sB>>>(feats, W, bias, out, N, maskBase);
    cudaEventRecord(g_evEmit, g_sB);

    // s0: join -> short scatter-copy tail
    cudaStreamWaitEvent(0, g_evEmit, 0);
    k_copy<<<1184, 256, 0, 0>>>(out, featBase);
}